// round 1
// baseline (speedup 1.0000x reference)
#include <cuda_runtime.h>
#include <math_constants.h>

#define HDIM   1536
#define NHEADS 12
#define NKV    2
#define DHEAD  128
#define GQA    6
#define MAXC   131072
#define QK_SCALE 0.08838834764831845f   // 128^-0.5

#define CS     512
#define NCHUNK (MAXC / CS)              // 256

// ---- scratch (no allocs allowed) ----
__device__ float g_q [NHEADS * DHEAD];           // pre-scaled q
__device__ float g_kv[2 * NKV * DHEAD];          // new k rows, then new v rows
__device__ float g_pm[NKV * NCHUNK * GQA];       // per-chunk max
__device__ float g_pz[NKV * NCHUNK * GQA];       // per-chunk sumexp
__device__ float g_po[NKV * NCHUNK * GQA * DHEAD]; // per-chunk weighted V
__device__ float g_out[NHEADS * DHEAD];          // attention output

// =====================================================================
// K1: q/k/v projections. 2048 rows total, one warp per row.
// =====================================================================
__global__ __launch_bounds__(256) void qkv_kernel(
    const float* __restrict__ x,
    const float* __restrict__ Wq,
    const float* __restrict__ Wk,
    const float* __restrict__ Wv)
{
    __shared__ float xs[HDIM];
    int tid = threadIdx.x;
    for (int i = tid; i < HDIM / 4; i += 256)
        ((float4*)xs)[i] = ((const float4*)x)[i];
    __syncthreads();

    int warp = tid >> 5, lane = tid & 31;
    int R = blockIdx.x * 8 + warp;               // 0..2047
    const float* Wrow;
    float* dst;
    float scl = 1.0f;
    if (R < 1536)      { Wrow = Wq + (long)R * HDIM;          dst = g_q  + R;                      scl = QK_SCALE; }
    else if (R < 1792) { Wrow = Wk + (long)(R - 1536) * HDIM; dst = g_kv + (R - 1536); }
    else               { Wrow = Wv + (long)(R - 1792) * HDIM; dst = g_kv + NKV * DHEAD + (R - 1792); }

    const float4* W4 = (const float4*)Wrow;
    const float4* x4 = (const float4*)xs;
    float s = 0.0f;
#pragma unroll
    for (int i = 0; i < 12; i++) {
        float4 w = W4[i * 32 + lane];
        float4 v = x4[i * 32 + lane];
        s += w.x * v.x + w.y * v.y + w.z * v.z + w.w * v.w;
    }
#pragma unroll
    for (int o = 16; o; o >>= 1) s += __shfl_xor_sync(0xffffffffu, s, o);
    if (lane == 0) *dst = s * scl;
}

// =====================================================================
// K2: flash-decode over one chunk of CS positions for one kv head.
// grid = (NCHUNK, NKV), 256 threads.
// =====================================================================
__global__ __launch_bounds__(256) void attn_kernel(
    const float* __restrict__ Kc,
    const float* __restrict__ Vc,
    const int*   __restrict__ pos_p)
{
    __shared__ float qs[GQA * DHEAD];     // 3 KB
    __shared__ float ss[GQA][CS];         // 12 KB: scores -> exp weights

    const int tid = threadIdx.x;
    const int c = blockIdx.x, g = blockIdx.y;
    const int pos = *pos_p;
    const int cb = c * CS;

    for (int i = tid; i < GQA * DHEAD / 4; i += 256)
        ((float4*)qs)[i] = ((const float4*)(g_q + g * GQA * DHEAD))[i];
    __syncthreads();

    const int lane = tid & 31, warp = tid >> 5;
    const int sg = lane >> 3;             // position sub-group 0..3
    const int ll = lane & 7;              // dim lanelet 0..7

    // q held in registers: head h, float4 j covers dims j*32 + ll*4 .. +3
    float4 qr[GQA][4];
    {
        const float4* q4 = (const float4*)qs;
#pragma unroll
        for (int h = 0; h < GQA; h++)
#pragma unroll
            for (int j = 0; j < 4; j++)
                qr[h][j] = q4[h * 32 + j * 8 + ll];
    }

    const float* Kbase = Kc + (long)g * MAXC * DHEAD;

    // ---- phase 1: scores ----
    for (int it = 0; it < CS / 32; ++it) {
        int li = it * 32 + warp * 4 + sg;        // local position
        int gl = cb + li;                        // global position
        const float4* krow = (gl == pos)
            ? (const float4*)(g_kv + g * DHEAD)
            : (const float4*)(Kbase + (long)gl * DHEAD);
        float p[GQA];
#pragma unroll
        for (int h = 0; h < GQA; h++) p[h] = 0.0f;
#pragma unroll
        for (int j = 0; j < 4; j++) {
            float4 k = krow[j * 8 + ll];         // 8 lanelets -> 128B coalesced
#pragma unroll
            for (int h = 0; h < GQA; h++) {
                p[h] += qr[h][j].x * k.x + qr[h][j].y * k.y
                      + qr[h][j].z * k.z + qr[h][j].w * k.w;
            }
        }
#pragma unroll
        for (int o = 1; o < 8; o <<= 1)
#pragma unroll
            for (int h = 0; h < GQA; h++)
                p[h] += __shfl_xor_sync(0xffffffffu, p[h], o);
        if (ll == 0) {
            bool valid = (gl <= pos);
#pragma unroll
            for (int h = 0; h < GQA; h++)
                ss[h][li] = valid ? p[h] : -CUDART_INF_F;
        }
    }
    __syncthreads();

    // ---- phase 2: per-head max, exp, partial Z ----
    if (warp < GQA) {
        int h = warp;
        float m = -CUDART_INF_F;
#pragma unroll
        for (int i = 0; i < CS / 32; i++) m = fmaxf(m, ss[h][lane + i * 32]);
#pragma unroll
        for (int o = 16; o; o >>= 1) m = fmaxf(m, __shfl_xor_sync(0xffffffffu, m, o));
        float mc = (m < -3e38f) ? 0.0f : m;      // fully-masked chunk guard
        float z = 0.0f;
#pragma unroll
        for (int i = 0; i < CS / 32; i++) {
            float e = __expf(ss[h][lane + i * 32] - mc);
            ss[h][lane + i * 32] = e;
            z += e;
        }
#pragma unroll
        for (int o = 16; o; o >>= 1) z += __shfl_xor_sync(0xffffffffu, z, o);
        if (lane == 0) {
            g_pm[(g * NCHUNK + c) * GQA + h] = m;   // raw max (may be -inf)
            g_pz[(g * NCHUNK + c) * GQA + h] = z;
        }
    }
    __syncthreads();

    // ---- phase 3: weighted V accumulation (dim-parallel) ----
    const int d = tid & 127;
    const int half = tid >> 7;
    const int h0 = half * 3;
    const float* Vbase = Vc + (long)g * MAXC * DHEAD;
    const float vnew = g_kv[NKV * DHEAD + g * DHEAD + d];
    float a0 = 0.0f, a1 = 0.0f, a2 = 0.0f;

    for (int l = 0; l < CS; l += 4) {
        float e0[4], e1[4], e2[4];
        *(float4*)e0 = *(const float4*)&ss[h0 + 0][l];
        *(float4*)e1 = *(const float4*)&ss[h0 + 1][l];
        *(float4*)e2 = *(const float4*)&ss[h0 + 2][l];
#pragma unroll
        for (int j = 0; j < 4; j++) {
            int gl = cb + l + j;
            float v = (gl == pos) ? vnew : Vbase[(long)gl * DHEAD + d];
            a0 += e0[j] * v;
            a1 += e1[j] * v;
            a2 += e2[j] * v;
        }
    }
    float* po = g_po + ((long)(g * NCHUNK + c) * GQA) * DHEAD;
    po[(h0 + 0) * DHEAD + d] = a0;
    po[(h0 + 1) * DHEAD + d] = a1;
    po[(h0 + 2) * DHEAD + d] = a2;
}

// =====================================================================
// K3: combine chunk partials (log-sum-exp merge). 12 blocks x 128 thr.
// =====================================================================
__global__ __launch_bounds__(128) void combine_kernel()
{
    const int hh = blockIdx.x;               // 0..11
    const int g = hh / GQA, h = hh % GQA;
    __shared__ float fs[NCHUNK];
    __shared__ float Msh, Zsh;
    const int tid = threadIdx.x, lane = tid & 31, warp = tid >> 5;

    if (warp == 0) {
        float m = -CUDART_INF_F;
#pragma unroll
        for (int i = 0; i < NCHUNK / 32; i++)
            m = fmaxf(m, g_pm[(g * NCHUNK + lane + i * 32) * GQA + h]);
#pragma unroll
        for (int o = 16; o; o >>= 1) m = fmaxf(m, __shfl_xor_sync(0xffffffffu, m, o));
        if (lane == 0) Msh = m;
    }
    __syncthreads();
    const float M = Msh;
    if (warp == 0) {
        float z = 0.0f;
#pragma unroll
        for (int i = 0; i < NCHUNK / 32; i++) {
            int cc = lane + i * 32;
            float f = __expf(g_pm[(g * NCHUNK + cc) * GQA + h] - M);  // -inf -> 0
            fs[cc] = f;
            z += f * g_pz[(g * NCHUNK + cc) * GQA + h];
        }
#pragma unroll
        for (int o = 16; o; o >>= 1) z += __shfl_xor_sync(0xffffffffu, z, o);
        if (lane == 0) Zsh = z;
    }
    __syncthreads();
    const float Z = Zsh;
    const int d = tid;
    float acc = 0.0f;
    for (int cc = 0; cc < NCHUNK; cc++)
        acc += fs[cc] * g_po[((long)(g * NCHUNK + cc) * GQA + h) * DHEAD + d];
    g_out[hh * DHEAD + d] = acc / Z;
}

// =====================================================================
// K4: y = Wo @ out. 1536 rows, one warp per row.
// =====================================================================
__global__ __launch_bounds__(256) void oproj_kernel(
    const float* __restrict__ Wo, float* __restrict__ y)
{
    __shared__ float os[HDIM];
    const int tid = threadIdx.x;
    for (int i = tid; i < HDIM / 4; i += 256)
        ((float4*)os)[i] = ((const float4*)g_out)[i];
    __syncthreads();

    const int warp = tid >> 5, lane = tid & 31;
    const int r = blockIdx.x * 8 + warp;
    const float4* W4 = (const float4*)(Wo + (long)r * HDIM);
    const float4* o4 = (const float4*)os;
    float s = 0.0f;
#pragma unroll
    for (int i = 0; i < 12; i++) {
        float4 w = W4[i * 32 + lane];
        float4 v = o4[i * 32 + lane];
        s += w.x * v.x + w.y * v.y + w.z * v.z + w.w * v.w;
    }
#pragma unroll
    for (int o = 16; o; o >>= 1) s += __shfl_xor_sync(0xffffffffu, s, o);
    if (lane == 0) y[r] = s;
}

// =====================================================================
// launch
// =====================================================================
extern "C" void kernel_launch(void* const* d_in, const int* in_sizes, int n_in,
                              void* d_out, int out_size)
{
    const float* x   = (const float*)d_in[0];   // hidden_states (1536)
    const float* Wq  = (const float*)d_in[1];
    const float* Wk  = (const float*)d_in[2];
    const float* Wv  = (const float*)d_in[3];
    const float* Wo  = (const float*)d_in[4];
    const float* Kc  = (const float*)d_in[5];   // (NKV, MAXC, DHEAD)
    const float* Vc  = (const float*)d_in[6];
    const int*   pos = (const int*)d_in[7];

    qkv_kernel<<<256, 256>>>(x, Wq, Wk, Wv);
    attn_kernel<<<dim3(NCHUNK, NKV), 256>>>(Kc, Vc, pos);
    combine_kernel<<<NHEADS, 128>>>();
    oproj_kernel<<<HDIM / 8, 256>>>(Wo, (float*)d_out);
}

// round 2
// speedup vs baseline: 1.3607x; 1.3607x over previous
#include <cuda_runtime.h>
#include <math_constants.h>

#define HDIM   1536
#define NHEADS 12
#define NKV    2
#define DHEAD  128
#define GQA    6
#define MAXC   131072
#define QK_SCALE 0.08838834764831845f   // 128^-0.5

#define CS     512
#define NCHUNK (MAXC / CS)              // 256
#define NSPLIT 8
#define CPB    (NCHUNK / NSPLIT)        // 32 chunks per combine block

// ---- scratch (no allocs allowed) ----
__device__ float g_q   [NHEADS * DHEAD];             // pre-scaled q
__device__ float g_kv  [2 * NKV * DHEAD];            // new k rows, then new v rows
__device__ float g_pm  [NKV * NCHUNK * GQA];         // per-chunk max
__device__ float g_pz  [NKV * NCHUNK * GQA];         // per-chunk sumexp
__device__ float g_po  [NKV * NCHUNK * GQA * DHEAD]; // per-chunk weighted V
__device__ float g_M   [NHEADS];                     // global max per head
__device__ float g_Z   [NHEADS];                     // global sumexp per head
__device__ float g_out2[NSPLIT][NHEADS * DHEAD];     // combine partials

// =====================================================================
// K1: q/k/v projections. 2048 rows, two rows per warp (MLP=24).
// grid 128 x 256.
// =====================================================================
__global__ __launch_bounds__(256) void qkv_kernel(
    const float* __restrict__ x,
    const float* __restrict__ Wq,
    const float* __restrict__ Wk,
    const float* __restrict__ Wv)
{
    __shared__ float xs[HDIM];
    const int tid = threadIdx.x;
    for (int i = tid; i < HDIM / 4; i += 256)
        ((float4*)xs)[i] = ((const float4*)x)[i];
    __syncthreads();

    const int warp = tid >> 5, lane = tid & 31;
    const int R0 = blockIdx.x * 16 + warp * 2;   // 0..2046, even

    const float *Wr[2]; float *dst[2]; float scl[2];
#pragma unroll
    for (int r = 0; r < 2; r++) {
        int R = R0 + r;
        if (R < 1536)      { Wr[r] = Wq + (long)R * HDIM;          dst[r] = g_q  + R;                      scl[r] = QK_SCALE; }
        else if (R < 1792) { Wr[r] = Wk + (long)(R - 1536) * HDIM; dst[r] = g_kv + (R - 1536);             scl[r] = 1.0f; }
        else               { Wr[r] = Wv + (long)(R - 1792) * HDIM; dst[r] = g_kv + NKV * DHEAD + (R-1792); scl[r] = 1.0f; }
    }

    const float4* W0 = (const float4*)Wr[0];
    const float4* W1 = (const float4*)Wr[1];
    const float4* x4 = (const float4*)xs;
    float s0 = 0.0f, s1 = 0.0f;
#pragma unroll
    for (int i = 0; i < 12; i++) {
        float4 a = W0[i * 32 + lane];
        float4 b = W1[i * 32 + lane];
        float4 v = x4[i * 32 + lane];
        s0 += a.x * v.x + a.y * v.y + a.z * v.z + a.w * v.w;
        s1 += b.x * v.x + b.y * v.y + b.z * v.z + b.w * v.w;
    }
#pragma unroll
    for (int o = 16; o; o >>= 1) {
        s0 += __shfl_xor_sync(0xffffffffu, s0, o);
        s1 += __shfl_xor_sync(0xffffffffu, s1, o);
    }
    if (lane == 0) { *dst[0] = s0 * scl[0]; *dst[1] = s1 * scl[1]; }
}

// =====================================================================
// K2: flash-decode chunk. grid (NCHUNK, NKV), 256 threads.
// =====================================================================
__global__ __launch_bounds__(256) void attn_kernel(
    const float* __restrict__ Kc,
    const float* __restrict__ Vc,
    const int*   __restrict__ pos_p)
{
    __shared__ float qs[GQA * DHEAD];          // 3 KB   (phase 1)
    __shared__ float ss[GQA][CS];              // 12 KB  (scores -> weights)
    __shared__ float buf[8][GQA * DHEAD];      // 24 KB  (phase 3 reduction)

    const int tid = threadIdx.x;
    const int c = blockIdx.x, g = blockIdx.y;
    const int pos = *pos_p;
    const int cb = c * CS;
    const int lane = tid & 31, warp = tid >> 5;

    for (int i = tid; i < GQA * DHEAD / 4; i += 256)
        ((float4*)qs)[i] = ((const float4*)(g_q + g * GQA * DHEAD))[i];
    __syncthreads();

    // ---- phase 1: scores (4 positions per warp per iter, 8-lane dots) ----
    const int sg = lane >> 3;                  // position subgroup 0..3
    const int ll = lane & 7;                   // dim lanelet 0..7
    const float* Kbase = Kc + (long)g * MAXC * DHEAD;
    const float4* q4 = (const float4*)qs;

#pragma unroll 2
    for (int it = 0; it < CS / 32; ++it) {
        int li = it * 32 + warp * 4 + sg;
        int gl = cb + li;
        const float4* krow = (gl == pos)
            ? (const float4*)(g_kv + g * DHEAD)
            : (const float4*)(Kbase + (long)gl * DHEAD);
        float p[GQA];
#pragma unroll
        for (int h = 0; h < GQA; h++) p[h] = 0.0f;
#pragma unroll
        for (int j = 0; j < 4; j++) {
            float4 k = krow[j * 8 + ll];
#pragma unroll
            for (int h = 0; h < GQA; h++) {
                float4 q = q4[h * 32 + j * 8 + ll];
                p[h] += q.x * k.x + q.y * k.y + q.z * k.z + q.w * k.w;
            }
        }
#pragma unroll
        for (int o = 1; o < 8; o <<= 1)
#pragma unroll
            for (int h = 0; h < GQA; h++)
                p[h] += __shfl_xor_sync(0xffffffffu, p[h], o);
        if (ll == 0) {
            bool valid = (gl <= pos);
#pragma unroll
            for (int h = 0; h < GQA; h++)
                ss[h][li] = valid ? p[h] : -CUDART_INF_F;
        }
    }
    __syncthreads();

    // ---- phase 2: per-head chunk max, exp, partial Z ----
    if (warp < GQA) {
        const int h = warp;
        float m = -CUDART_INF_F;
#pragma unroll
        for (int i = 0; i < CS / 32; i++) m = fmaxf(m, ss[h][lane + i * 32]);
#pragma unroll
        for (int o = 16; o; o >>= 1) m = fmaxf(m, __shfl_xor_sync(0xffffffffu, m, o));
        float mc = (m < -3e38f) ? 0.0f : m;
        float z = 0.0f;
#pragma unroll
        for (int i = 0; i < CS / 32; i++) {
            float e = __expf(ss[h][lane + i * 32] - mc);
            ss[h][lane + i * 32] = e;
            z += e;
        }
#pragma unroll
        for (int o = 16; o; o >>= 1) z += __shfl_xor_sync(0xffffffffu, z, o);
        if (lane == 0) {
            g_pm[(g * NCHUNK + c) * GQA + h] = m;
            g_pz[(g * NCHUNK + c) * GQA + h] = z;
        }
    }
    __syncthreads();

    // ---- phase 3: weighted V. Warp-per-position, float4 rows. ----
    const float* Vbase = Vc + (long)g * MAXC * DHEAD;
    const float4* vnew4 = (const float4*)(g_kv + NKV * DHEAD + g * DHEAD);
    float4 acc[GQA];
#pragma unroll
    for (int h = 0; h < GQA; h++) acc[h] = make_float4(0.f, 0.f, 0.f, 0.f);

#pragma unroll 4
    for (int l = warp; l < CS; l += 8) {
        int gl = cb + l;
        float4 v = (gl == pos) ? vnew4[lane]
                               : ((const float4*)(Vbase + (long)gl * DHEAD))[lane];
        float e[GQA];
#pragma unroll
        for (int h = 0; h < GQA; h++) e[h] = ss[h][l];
#pragma unroll
        for (int h = 0; h < GQA; h++) {
            acc[h].x += e[h] * v.x;
            acc[h].y += e[h] * v.y;
            acc[h].z += e[h] * v.z;
            acc[h].w += e[h] * v.w;
        }
    }
    float4* b4 = (float4*)buf[warp];
#pragma unroll
    for (int h = 0; h < GQA; h++) b4[h * 32 + lane] = acc[h];
    __syncthreads();

    // cross-warp reduce + write chunk partial (192 float4 outputs)
    float4* po4 = (float4*)(g_po + (long)(g * NCHUNK + c) * GQA * DHEAD);
    for (int i = tid; i < GQA * DHEAD / 4; i += 256) {
        float4 s = ((float4*)buf[0])[i];
#pragma unroll
        for (int w = 1; w < 8; w++) {
            float4 t = ((float4*)buf[w])[i];
            s.x += t.x; s.y += t.y; s.z += t.z; s.w += t.w;
        }
        po4[i] = s;
    }
}

// =====================================================================
// K3a: global max + Z per head. 1 block, 12 warps.
// =====================================================================
__global__ __launch_bounds__(384) void combine_mz_kernel()
{
    const int warp = threadIdx.x >> 5, lane = threadIdx.x & 31;
    const int hh = warp, g = hh / GQA, h = hh % GQA;

    float m = -CUDART_INF_F;
#pragma unroll
    for (int i = 0; i < NCHUNK / 32; i++)
        m = fmaxf(m, g_pm[(g * NCHUNK + lane + i * 32) * GQA + h]);
#pragma unroll
    for (int o = 16; o; o >>= 1) m = fmaxf(m, __shfl_xor_sync(0xffffffffu, m, o));

    float z = 0.0f;
#pragma unroll
    for (int i = 0; i < NCHUNK / 32; i++) {
        int cc = lane + i * 32;
        z += __expf(g_pm[(g * NCHUNK + cc) * GQA + h] - m) * g_pz[(g * NCHUNK + cc) * GQA + h];
    }
#pragma unroll
    for (int o = 16; o; o >>= 1) z += __shfl_xor_sync(0xffffffffu, z, o);
    if (lane == 0) { g_M[hh] = m; g_Z[hh] = z; }
}

// =====================================================================
// K3b: accumulate chunk partials. grid (12, NSPLIT), 128 threads.
// =====================================================================
__global__ __launch_bounds__(128) void combine_acc_kernel()
{
    const int hh = blockIdx.x, s = blockIdx.y;
    const int g = hh / GQA, h = hh % GQA;
    const int tid = threadIdx.x;
    __shared__ float fs[CPB];

    const float M = g_M[hh];
    const float Zinv = 1.0f / g_Z[hh];

    if (tid < CPB) {
        int cc = s * CPB + tid;
        fs[tid] = __expf(g_pm[(g * NCHUNK + cc) * GQA + h] - M);
    }
    __syncthreads();

    float acc = 0.0f;
#pragma unroll 4
    for (int i = 0; i < CPB; i++) {
        int cc = s * CPB + i;
        acc += fs[i] * g_po[((long)(g * NCHUNK + cc) * GQA + h) * DHEAD + tid];
    }
    g_out2[s][hh * DHEAD + tid] = acc * Zinv;
}

// =====================================================================
// K4: y = Wo @ out. 1536 rows, two rows per warp. grid 96 x 256.
// =====================================================================
__global__ __launch_bounds__(256) void oproj_kernel(
    const float* __restrict__ Wo, float* __restrict__ y)
{
    __shared__ float os[HDIM];
    const int tid = threadIdx.x;
    for (int i = tid; i < HDIM; i += 256) {
        float s = 0.0f;
#pragma unroll
        for (int p = 0; p < NSPLIT; p++) s += g_out2[p][i];
        os[i] = s;
    }
    __syncthreads();

    const int warp = tid >> 5, lane = tid & 31;
    const int r0 = blockIdx.x * 16 + warp * 2;
    const float4* W0 = (const float4*)(Wo + (long)r0 * HDIM);
    const float4* W1 = (const float4*)(Wo + (long)(r0 + 1) * HDIM);
    const float4* o4 = (const float4*)os;
    float s0 = 0.0f, s1 = 0.0f;
#pragma unroll
    for (int i = 0; i < 12; i++) {
        float4 a = W0[i * 32 + lane];
        float4 b = W1[i * 32 + lane];
        float4 v = o4[i * 32 + lane];
        s0 += a.x * v.x + a.y * v.y + a.z * v.z + a.w * v.w;
        s1 += b.x * v.x + b.y * v.y + b.z * v.z + b.w * v.w;
    }
#pragma unroll
    for (int o = 16; o; o >>= 1) {
        s0 += __shfl_xor_sync(0xffffffffu, s0, o);
        s1 += __shfl_xor_sync(0xffffffffu, s1, o);
    }
    if (lane == 0) { y[r0] = s0; y[r0 + 1] = s1; }
}

// =====================================================================
// launch
// =====================================================================
extern "C" void kernel_launch(void* const* d_in, const int* in_sizes, int n_in,
                              void* d_out, int out_size)
{
    const float* x   = (const float*)d_in[0];
    const float* Wq  = (const float*)d_in[1];
    const float* Wk  = (const float*)d_in[2];
    const float* Wv  = (const float*)d_in[3];
    const float* Wo  = (const float*)d_in[4];
    const float* Kc  = (const float*)d_in[5];
    const float* Vc  = (const float*)d_in[6];
    const int*   pos = (const int*)d_in[7];

    qkv_kernel<<<128, 256>>>(x, Wq, Wk, Wv);
    attn_kernel<<<dim3(NCHUNK, NKV), 256>>>(Kc, Vc, pos);
    combine_mz_kernel<<<1, 384>>>();
    combine_acc_kernel<<<dim3(NHEADS, NSPLIT), 128>>>();
    oproj_kernel<<<96, 256>>>(Wo, (float*)d_out);
}

// round 3
// speedup vs baseline: 1.4411x; 1.0591x over previous
#include <cuda_runtime.h>
#include <math_constants.h>

#define HDIM   1536
#define NHEADS 12
#define NKV    2
#define DHEAD  128
#define GQA    6
#define MAXC   131072
#define QK_SCALE 0.08838834764831845f   // 128^-0.5

#define CS     256
#define NCHUNK (MAXC / CS)              // 512
#define NSPLIT 16
#define CPB    (NCHUNK / NSPLIT)        // 32 chunks per combine block

// ---- scratch (no allocs allowed) ----
__device__ float g_q   [NHEADS * DHEAD];             // pre-scaled q
__device__ float g_kv  [2 * NKV * DHEAD];            // new k rows, then new v rows
__device__ float g_pm  [NHEADS * NCHUNK];            // per-chunk max   [head][chunk]
__device__ float g_pz  [NHEADS * NCHUNK];            // per-chunk sumexp[head][chunk]
__device__ float g_po  [NHEADS * NCHUNK * DHEAD];    // chunk partials  [head][chunk][dim]
__device__ float g_M   [NHEADS];                     // global max per head
__device__ float g_Z   [NHEADS];                     // global sumexp per head
__device__ float g_out2[NSPLIT][NHEADS * DHEAD];     // combine partials

// =====================================================================
// K1: q/k/v projections. 2048 rows, two rows per warp.
// =====================================================================
__global__ __launch_bounds__(256) void qkv_kernel(
    const float* __restrict__ x,
    const float* __restrict__ Wq,
    const float* __restrict__ Wk,
    const float* __restrict__ Wv)
{
    __shared__ float xs[HDIM];
    const int tid = threadIdx.x;
    for (int i = tid; i < HDIM / 4; i += 256)
        ((float4*)xs)[i] = ((const float4*)x)[i];
    __syncthreads();

    const int warp = tid >> 5, lane = tid & 31;
    const int R0 = blockIdx.x * 16 + warp * 2;

    const float *Wr[2]; float *dst[2]; float scl[2];
#pragma unroll
    for (int r = 0; r < 2; r++) {
        int R = R0 + r;
        if (R < 1536)      { Wr[r] = Wq + (long)R * HDIM;          dst[r] = g_q  + R;                      scl[r] = QK_SCALE; }
        else if (R < 1792) { Wr[r] = Wk + (long)(R - 1536) * HDIM; dst[r] = g_kv + (R - 1536);             scl[r] = 1.0f; }
        else               { Wr[r] = Wv + (long)(R - 1792) * HDIM; dst[r] = g_kv + NKV * DHEAD + (R-1792); scl[r] = 1.0f; }
    }

    const float4* W0 = (const float4*)Wr[0];
    const float4* W1 = (const float4*)Wr[1];
    const float4* x4 = (const float4*)xs;
    float s0 = 0.0f, s1 = 0.0f;
#pragma unroll
    for (int i = 0; i < 12; i++) {
        float4 a = W0[i * 32 + lane];
        float4 b = W1[i * 32 + lane];
        float4 v = x4[i * 32 + lane];
        s0 += a.x * v.x + a.y * v.y + a.z * v.z + a.w * v.w;
        s1 += b.x * v.x + b.y * v.y + b.z * v.z + b.w * v.w;
    }
#pragma unroll
    for (int o = 16; o; o >>= 1) {
        s0 += __shfl_xor_sync(0xffffffffu, s0, o);
        s1 += __shfl_xor_sync(0xffffffffu, s1, o);
    }
    if (lane == 0) { *dst[0] = s0 * scl[0]; *dst[1] = s1 * scl[1]; }
}

// =====================================================================
// K2: flash-decode chunk. grid (NCHUNK, NKV), 256 threads.
// =====================================================================
__global__ __launch_bounds__(256) void attn_kernel(
    const float* __restrict__ Kc,
    const float* __restrict__ Vc,
    const int*   __restrict__ pos_p)
{
    __shared__ float qs[GQA * DHEAD];          // 3 KB
    __shared__ float ss[GQA][CS];              // 6 KB
    __shared__ float buf[8][GQA * DHEAD];      // 24 KB

    const int tid = threadIdx.x;
    const int c = blockIdx.x, g = blockIdx.y;
    const int pos = *pos_p;
    const int cb = c * CS;
    const int lane = tid & 31, warp = tid >> 5;

    for (int i = tid; i < GQA * DHEAD / 4; i += 256)
        ((float4*)qs)[i] = ((const float4*)(g_q + g * GQA * DHEAD))[i];
    __syncthreads();

    // ---- phase 1: scores (4 positions per warp per iter, 8-lane dots) ----
    const int sg = lane >> 3;
    const int ll = lane & 7;
    const float* Kbase = Kc + (long)g * MAXC * DHEAD;
    const float4* q4 = (const float4*)qs;

#pragma unroll 4
    for (int it = 0; it < CS / 32; ++it) {
        int li = it * 32 + warp * 4 + sg;
        int gl = cb + li;
        const float4* krow = (gl == pos)
            ? (const float4*)(g_kv + g * DHEAD)
            : (const float4*)(Kbase + (long)gl * DHEAD);
        float p[GQA];
#pragma unroll
        for (int h = 0; h < GQA; h++) p[h] = 0.0f;
#pragma unroll
        for (int j = 0; j < 4; j++) {
            float4 k = krow[j * 8 + ll];
#pragma unroll
            for (int h = 0; h < GQA; h++) {
                float4 q = q4[h * 32 + j * 8 + ll];
                p[h] += q.x * k.x + q.y * k.y + q.z * k.z + q.w * k.w;
            }
        }
#pragma unroll
        for (int o = 1; o < 8; o <<= 1)
#pragma unroll
            for (int h = 0; h < GQA; h++)
                p[h] += __shfl_xor_sync(0xffffffffu, p[h], o);
        if (ll == 0) {
            bool valid = (gl <= pos);
#pragma unroll
            for (int h = 0; h < GQA; h++)
                ss[h][li] = valid ? p[h] : -CUDART_INF_F;
        }
    }
    __syncthreads();

    // ---- phase 2: per-head chunk max, exp, partial Z ----
    if (warp < GQA) {
        const int h = warp;
        float m = -CUDART_INF_F;
#pragma unroll
        for (int i = 0; i < CS / 32; i++) m = fmaxf(m, ss[h][lane + i * 32]);
#pragma unroll
        for (int o = 16; o; o >>= 1) m = fmaxf(m, __shfl_xor_sync(0xffffffffu, m, o));
        float mc = (m < -3e38f) ? 0.0f : m;
        float z = 0.0f;
#pragma unroll
        for (int i = 0; i < CS / 32; i++) {
            float e = __expf(ss[h][lane + i * 32] - mc);
            ss[h][lane + i * 32] = e;
            z += e;
        }
#pragma unroll
        for (int o = 16; o; o >>= 1) z += __shfl_xor_sync(0xffffffffu, z, o);
        if (lane == 0) {
            g_pm[(g * GQA + h) * NCHUNK + c] = m;
            g_pz[(g * GQA + h) * NCHUNK + c] = z;
        }
    }
    __syncthreads();

    // ---- phase 3: weighted V. Warp-per-position, float4 rows. ----
    const float* Vbase = Vc + (long)g * MAXC * DHEAD;
    const float4* vnew4 = (const float4*)(g_kv + NKV * DHEAD + g * DHEAD);
    float4 acc[GQA];
#pragma unroll
    for (int h = 0; h < GQA; h++) acc[h] = make_float4(0.f, 0.f, 0.f, 0.f);

#pragma unroll 4
    for (int l = warp; l < CS; l += 8) {
        int gl = cb + l;
        float4 v = (gl == pos) ? vnew4[lane]
                               : ((const float4*)(Vbase + (long)gl * DHEAD))[lane];
        float e[GQA];
#pragma unroll
        for (int h = 0; h < GQA; h++) e[h] = ss[h][l];
#pragma unroll
        for (int h = 0; h < GQA; h++) {
            acc[h].x += e[h] * v.x;
            acc[h].y += e[h] * v.y;
            acc[h].z += e[h] * v.z;
            acc[h].w += e[h] * v.w;
        }
    }
    float4* b4 = (float4*)buf[warp];
#pragma unroll
    for (int h = 0; h < GQA; h++) b4[h * 32 + lane] = acc[h];
    __syncthreads();

    // cross-warp reduce + write chunk partials: g_po[head][chunk][dim]
    for (int i = tid; i < GQA * DHEAD / 4; i += 256) {
        float4 s = ((float4*)buf[0])[i];
#pragma unroll
        for (int w = 1; w < 8; w++) {
            float4 t = ((float4*)buf[w])[i];
            s.x += t.x; s.y += t.y; s.z += t.z; s.w += t.w;
        }
        int h = i >> 5;                 // 32 float4 per head row
        int d4 = i & 31;
        ((float4*)(g_po + ((long)(g * GQA + h) * NCHUNK + c) * DHEAD))[d4] = s;
    }
}

// =====================================================================
// K3a: global max + Z per head. 1 block, 12 warps, contiguous float4.
// =====================================================================
__global__ __launch_bounds__(384) void combine_mz_kernel()
{
    const int warp = threadIdx.x >> 5, lane = threadIdx.x & 31;
    const int hh = warp;

    const float4* pm4 = (const float4*)(g_pm + hh * NCHUNK);
    const float4* pz4 = (const float4*)(g_pz + hh * NCHUNK);

    float m = -CUDART_INF_F;
    float4 mv[NCHUNK / 128];
#pragma unroll
    for (int i = 0; i < NCHUNK / 128; i++) {
        mv[i] = pm4[i * 32 + lane];
        m = fmaxf(m, fmaxf(fmaxf(mv[i].x, mv[i].y), fmaxf(mv[i].z, mv[i].w)));
    }
#pragma unroll
    for (int o = 16; o; o >>= 1) m = fmaxf(m, __shfl_xor_sync(0xffffffffu, m, o));

    float z = 0.0f;
#pragma unroll
    for (int i = 0; i < NCHUNK / 128; i++) {
        float4 zv = pz4[i * 32 + lane];
        z += __expf(mv[i].x - m) * zv.x + __expf(mv[i].y - m) * zv.y
           + __expf(mv[i].z - m) * zv.z + __expf(mv[i].w - m) * zv.w;
    }
#pragma unroll
    for (int o = 16; o; o >>= 1) z += __shfl_xor_sync(0xffffffffu, z, o);
    if (lane == 0) { g_M[hh] = m; g_Z[hh] = z; }
}

// =====================================================================
// K3b: accumulate chunk partials. grid (12, NSPLIT), 256 thr (8 warps).
// Warp-per-chunk-row, float4 loads, cross-warp smem reduce.
// =====================================================================
__global__ __launch_bounds__(256) void combine_acc_kernel()
{
    const int hh = blockIdx.x, s = blockIdx.y;
    const int tid = threadIdx.x, lane = tid & 31, warp = tid >> 5;
    __shared__ float4 rb[8][32];

    const float M = g_M[hh];
    const float Zinv = 1.0f / g_Z[hh];
    const int c0 = s * CPB;

    float4 acc = make_float4(0.f, 0.f, 0.f, 0.f);
#pragma unroll
    for (int i = 0; i < CPB / 8; i++) {          // 4 chunks per warp
        int cc = c0 + warp + i * 8;
        float f = __expf(g_pm[hh * NCHUNK + cc] - M);
        float4 v = ((const float4*)(g_po + ((long)hh * NCHUNK + cc) * DHEAD))[lane];
        acc.x += f * v.x; acc.y += f * v.y; acc.z += f * v.z; acc.w += f * v.w;
    }
    rb[warp][lane] = acc;
    __syncthreads();

    if (warp == 0) {
        float4 t = rb[0][lane];
#pragma unroll
        for (int w = 1; w < 8; w++) {
            float4 u = rb[w][lane];
            t.x += u.x; t.y += u.y; t.z += u.z; t.w += u.w;
        }
        t.x *= Zinv; t.y *= Zinv; t.z *= Zinv; t.w *= Zinv;
        ((float4*)(g_out2[s] + hh * DHEAD))[lane] = t;
    }
}

// =====================================================================
// K4: y = Wo @ out. 1536 rows, two rows per warp.
// =====================================================================
__global__ __launch_bounds__(256) void oproj_kernel(
    const float* __restrict__ Wo, float* __restrict__ y)
{
    __shared__ float os[HDIM];
    const int tid = threadIdx.x;
    for (int i = tid; i < HDIM; i += 256) {
        float s = 0.0f;
#pragma unroll
        for (int p = 0; p < NSPLIT; p++) s += g_out2[p][i];
        os[i] = s;
    }
    __syncthreads();

    const int warp = tid >> 5, lane = tid & 31;
    const int r0 = blockIdx.x * 16 + warp * 2;
    const float4* W0 = (const float4*)(Wo + (long)r0 * HDIM);
    const float4* W1 = (const float4*)(Wo + (long)(r0 + 1) * HDIM);
    const float4* o4 = (const float4*)os;
    float s0 = 0.0f, s1 = 0.0f;
#pragma unroll
    for (int i = 0; i < 12; i++) {
        float4 a = W0[i * 32 + lane];
        float4 b = W1[i * 32 + lane];
        float4 v = o4[i * 32 + lane];
        s0 += a.x * v.x + a.y * v.y + a.z * v.z + a.w * v.w;
        s1 += b.x * v.x + b.y * v.y + b.z * v.z + b.w * v.w;
    }
#pragma unroll
    for (int o = 16; o; o >>= 1) {
        s0 += __shfl_xor_sync(0xffffffffu, s0, o);
        s1 += __shfl_xor_sync(0xffffffffu, s1, o);
    }
    if (lane == 0) { y[r0] = s0; y[r0 + 1] = s1; }
}

// =====================================================================
// launch
// =====================================================================
extern "C" void kernel_launch(void* const* d_in, const int* in_sizes, int n_in,
                              void* d_out, int out_size)
{
    const float* x   = (const float*)d_in[0];
    const float* Wq  = (const float*)d_in[1];
    const float* Wk  = (const float*)d_in[2];
    const float* Wv  = (const float*)d_in[3];
    const float* Wo  = (const float*)d_in[4];
    const float* Kc  = (const float*)d_in[5];
    const float* Vc  = (const float*)d_in[6];
    const int*   pos = (const int*)d_in[7];

    qkv_kernel<<<128, 256>>>(x, Wq, Wk, Wv);
    attn_kernel<<<dim3(NCHUNK, NKV), 256>>>(Kc, Vc, pos);
    combine_mz_kernel<<<1, 384>>>();
    combine_acc_kernel<<<dim3(NHEADS, NSPLIT), 256>>>();
    oproj_kernel<<<96, 256>>>(Wo, (float*)d_out);
}